// round 13
// baseline (speedup 1.0000x reference)
#include <cuda_runtime.h>

#define Bz 64
#define Tz 512
#define Fz 512
#define Hz 1024
#define Gz 4096   // 4*H
#define NBLK 128
#define NTH 512
#define OUT_HOFF (Bz*Tz*Hz)                 // 33,554,432
#define OUT_COFF (OUT_HOFF + 2*Bz*Hz)       // + 131,072

typedef unsigned long long ull;

// ---------------- static device scratch (no allocations allowed) ----------------
__device__ float g_pre[(size_t)Tz * Bz * Gz];       // [T][B][4H] input-GEMM + biases
__device__ float g_WT[3][(size_t)NBLK * Hz * 32];   // transposed weights: [jblk][k][32 ln]
__device__ float g_h0T[2][Hz * Bz];                 // layer0 h, TRANSPOSED [k][b]
__device__ float g_h1T[2][Hz * Bz];                 // layer1 h, TRANSPOSED [k][b]
__device__ unsigned g_count;
__device__ volatile unsigned g_sense;

// fast sigmoid / tanh: __expf (MUFU.EX2) + __fdividef (MUFU.RCP), ~1e-7 rel err.
// tanh via |x| keeps e in (0,1] -> no overflow, well-conditioned divide.
__device__ __forceinline__ float sigm(float x) {
    return __fdividef(1.f, 1.f + __expf(-x));
}
__device__ __forceinline__ float tanh_f(float x) {
    float a = fabsf(x);
    float e = __expf(-2.f * a);
    float t = __fdividef(1.f - e, 1.f + e);
    return copysignf(t, x);
}

// ---- packed fp32x2 FMA (sm_10x FFMA2; only reachable via PTX) ----
__device__ __forceinline__ void ffma2(ull &d, ull a, ull b) {
    asm("fma.rn.f32x2 %0, %1, %2, %0;" : "+l"(d) : "l"(a), "l"(b));
}
__device__ __forceinline__ ull pack2(float x, float y) {
    ull r; asm("mov.b64 %0, {%1, %2};" : "=l"(r) : "f"(x), "f"(y)); return r;
}
__device__ __forceinline__ ull dup2(float x) { return pack2(x, x); }
__device__ __forceinline__ float2 unpack2(ull v) {
    float2 r; asm("mov.b64 {%0, %1}, %2;" : "=f"(r.x), "=f"(r.y) : "l"(v)); return r;
}

// Grid-wide barrier. Grid=128 blocks <= SM count => all co-resident, no deadlock.
__device__ __forceinline__ void grid_bar(unsigned &sense) {
    __syncthreads();
    if (threadIdx.x == 0) {
        unsigned s = sense + 1u;
        sense = s;
        __threadfence();
        unsigned arr = atomicAdd(&g_count, 1u);
        if (arr == gridDim.x - 1) {
            g_count = 0;
            __threadfence();
            g_sense = s;
        } else {
            while (g_sense != s) { }
            __threadfence();
        }
    }
    __syncthreads();
}

// ============================================================================
// Weight pre-transpose: g_WT[m][jblk][k][ln] = W[(ln>>3)*H + jblk*8 + (ln&7)][k]
// ============================================================================
__global__ __launch_bounds__(256) void lstm_wt(
    const float* __restrict__ W0, const float* __restrict__ W1,
    const float* __restrict__ W2)
{
    __shared__ float tile[32][33];
    const int jblk = blockIdx.x;
    const int k0   = blockIdx.y * 32;
    const int m    = blockIdx.z;
    const float* W = (m == 0) ? W0 : (m == 1) ? W1 : W2;
    float* dst = g_WT[m];
    const int lane = threadIdx.x & 31, grp = threadIdx.x >> 5;
#pragma unroll
    for (int i = 0; i < 4; i++) {
        int ln = grp + i * 8;
        int row = (ln >> 3) * Hz + jblk * 8 + (ln & 7);
        tile[ln][lane] = W[(size_t)row * Hz + k0 + lane];   // coalesced over k
    }
    __syncthreads();
#pragma unroll
    for (int i = 0; i < 4; i++) {
        int k = grp + i * 8;
        dst[((size_t)jblk * Hz + k0 + k) * 32 + lane] = tile[lane][k];  // coalesced over ln
    }
}

// ============================================================================
// Phase A: g_pre[t][b][n] = sum_k x[b][t][k] * Wi0[n][k] + bi0[n] + bh0[n]
// (unchanged — not the bottleneck)
// ============================================================================
__global__ __launch_bounds__(256) void lstm_pre(
    const float* __restrict__ x, const float* __restrict__ Wi0,
    const float* __restrict__ bi0, const float* __restrict__ bh0)
{
    __shared__ float As[16][132];
    __shared__ float Bs[16][132];

    const int tid = threadIdx.x;
    const int n0 = blockIdx.x * 128;
    const int m0 = blockIdx.y * 128;
    const int ty = tid >> 4, tx = tid & 15;

    const int r0 = tid >> 2,          kq0 = tid & 3;
    const int r1 = (tid + 256) >> 2,  kq1 = (tid + 256) & 3;
    const int gr0 = m0 + r0, gr1 = m0 + r1;
    const float* xa0 = &x[((size_t)((gr0 & 63) * Tz + (gr0 >> 6))) * Fz + kq0 * 4];
    const float* xa1 = &x[((size_t)((gr1 & 63) * Tz + (gr1 >> 6))) * Fz + kq1 * 4];
    const float* wb0 = &Wi0[((size_t)(n0 + r0)) * Fz + kq0 * 4];
    const float* wb1 = &Wi0[((size_t)(n0 + r1)) * Fz + kq1 * 4];

    ull acc2[4][8];
#pragma unroll
    for (int p = 0; p < 4; p++)
#pragma unroll
        for (int j = 0; j < 8; j++) acc2[p][j] = 0ull;

    float4 pa0 = *(const float4*)xa0;
    float4 pa1 = *(const float4*)xa1;
    float4 pb0 = *(const float4*)wb0;
    float4 pb1 = *(const float4*)wb1;

    for (int kc = 0; kc < Fz / 16; kc++) {
        __syncthreads();
        As[kq0 * 4 + 0][r0] = pa0.x; As[kq0 * 4 + 1][r0] = pa0.y;
        As[kq0 * 4 + 2][r0] = pa0.z; As[kq0 * 4 + 3][r0] = pa0.w;
        As[kq1 * 4 + 0][r1] = pa1.x; As[kq1 * 4 + 1][r1] = pa1.y;
        As[kq1 * 4 + 2][r1] = pa1.z; As[kq1 * 4 + 3][r1] = pa1.w;
        Bs[kq0 * 4 + 0][r0] = pb0.x; Bs[kq0 * 4 + 1][r0] = pb0.y;
        Bs[kq0 * 4 + 2][r0] = pb0.z; Bs[kq0 * 4 + 3][r0] = pb0.w;
        Bs[kq1 * 4 + 0][r1] = pb1.x; Bs[kq1 * 4 + 1][r1] = pb1.y;
        Bs[kq1 * 4 + 2][r1] = pb1.z; Bs[kq1 * 4 + 3][r1] = pb1.w;
        __syncthreads();
        if (kc < Fz / 16 - 1) {
            int off = (kc + 1) * 16;
            pa0 = *(const float4*)(xa0 + off);
            pa1 = *(const float4*)(xa1 + off);
            pb0 = *(const float4*)(wb0 + off);
            pb1 = *(const float4*)(wb1 + off);
        }
#pragma unroll
        for (int kk = 0; kk < 16; kk++) {
            ulonglong2 a01 = *(const ulonglong2*)&As[kk][ty * 8];
            ulonglong2 a23 = *(const ulonglong2*)&As[kk][ty * 8 + 4];
            float bb[8];
            *(float4*)&bb[0] = *(const float4*)&Bs[kk][tx * 8];
            *(float4*)&bb[4] = *(const float4*)&Bs[kk][tx * 8 + 4];
#pragma unroll
            for (int j = 0; j < 8; j++) {
                ull wd = dup2(bb[j]);
                ffma2(acc2[0][j], a01.x, wd);
                ffma2(acc2[1][j], a01.y, wd);
                ffma2(acc2[2][j], a23.x, wd);
                ffma2(acc2[3][j], a23.y, wd);
            }
        }
    }

    float accf[8][8];
#pragma unroll
    for (int p = 0; p < 4; p++)
#pragma unroll
        for (int j = 0; j < 8; j++) {
            float2 v = unpack2(acc2[p][j]);
            accf[2 * p][j] = v.x;
            accf[2 * p + 1][j] = v.y;
        }

    float bsv[8];
#pragma unroll
    for (int j = 0; j < 8; j++) {
        int n = n0 + tx * 8 + j;
        bsv[j] = bi0[n] + bh0[n];
    }
#pragma unroll
    for (int i = 0; i < 8; i++) {
        size_t off = (size_t)(m0 + ty * 8 + i) * Gz + n0 + tx * 8;
        float4 v0, v1;
        v0.x = accf[i][0] + bsv[0]; v0.y = accf[i][1] + bsv[1];
        v0.z = accf[i][2] + bsv[2]; v0.w = accf[i][3] + bsv[3];
        v1.x = accf[i][4] + bsv[4]; v1.y = accf[i][5] + bsv[5];
        v1.z = accf[i][6] + bsv[6]; v1.w = accf[i][7] + bsv[7];
        *(float4*)&g_pre[off]     = v0;
        *(float4*)&g_pre[off + 4] = v1;
    }
}

// ============================================================================
// Persistent recurrent kernel, 512 threads = 8 k-groups x 64 threads.
// Double-buffered SMEM tiles (1 sync per kc), w stored PRE-DUPLICATED so the
// inner loop is 4x LDS.128 + 16x FFMA2 with zero repacking MOVs.
// Per-group tile region (4096 floats): hs0|hs1|ws0|ws1 (1024 each).
// ============================================================================
#define POOL_FLOATS 32768
#define TILE_OFF(g) ((g) * 4096)
#define PART_OFF(g) (((g) - 1) * 2304)
#define SMEM_BYTES  ((POOL_FLOATS + 2304 + 1024 + 32) * 4)

__device__ __forceinline__ void gemm_ks(
    const float* __restrict__ hT,   // group's h slice: [(128k) x 64b] contiguous
    const float* __restrict__ WT,   // group's w slice: [(128k) x 32ln] contiguous
    int wtid, ull (&acc)[4][4], float* __restrict__ tb)
{
    const int b0  = (wtid >> 3) * 8;
    const int lnd = (wtid & 7) * 8;          // dup'd w float offset (= 2*ln0)
    const int h4  = wtid * 4;
    const int wka = wtid >> 3;               // source k-row of first w float4
    const int wdst_a = wka * 64 + lnd;       // dup dest (row stride 64)
    const int wdst_b = (wka + 8) * 64 + lnd;

    float4 ph0 = *(const float4*)(hT + h4);
    float4 ph1 = *(const float4*)(hT + 256 + h4);
    float4 ph2 = *(const float4*)(hT + 512 + h4);
    float4 ph3 = *(const float4*)(hT + 768 + h4);
    float4 pw0 = *(const float4*)(WT + h4);
    float4 pw1 = *(const float4*)(WT + 256 + h4);

    for (int kc = 0; kc < 8; kc++) {
        float* const hsc = tb + ((kc & 1) << 10);
        float* const wsc = tb + 2048 + ((kc & 1) << 10);
        *(float4*)(hsc + h4)       = ph0;
        *(float4*)(hsc + 256 + h4) = ph1;
        *(float4*)(hsc + 512 + h4) = ph2;
        *(float4*)(hsc + 768 + h4) = ph3;
        float4 d;
        d.x = pw0.x; d.y = pw0.x; d.z = pw0.y; d.w = pw0.y;
        *(float4*)(wsc + wdst_a) = d;
        d.x = pw0.z; d.y = pw0.z; d.z = pw0.w; d.w = pw0.w;
        *(float4*)(wsc + wdst_a + 4) = d;
        d.x = pw1.x; d.y = pw1.x; d.z = pw1.y; d.w = pw1.y;
        *(float4*)(wsc + wdst_b) = d;
        d.x = pw1.z; d.y = pw1.z; d.z = pw1.w; d.w = pw1.w;
        *(float4*)(wsc + wdst_b + 4) = d;
        __syncthreads();    // single sync per kc: buf[cur] ready; buf[cur^1] free
        if (kc < 7) {       // prefetch next tile into regs (overlaps compute)
            const float* hn = hT + (kc + 1) * 1024;
            const float* wn = WT + (kc + 1) * 512;
            ph0 = *(const float4*)(hn + h4);
            ph1 = *(const float4*)(hn + 256 + h4);
            ph2 = *(const float4*)(hn + 512 + h4);
            ph3 = *(const float4*)(hn + 768 + h4);
            pw0 = *(const float4*)(wn + h4);
            pw1 = *(const float4*)(wn + 256 + h4);
        }
#pragma unroll 4
        for (int kk = 0; kk < 16; kk++) {
            const float* hrow = hsc + kk * 64 + b0;
            ulonglong2 hA = *(const ulonglong2*)(hrow);      // b-pairs (0,1),(2,3)
            ulonglong2 hB = *(const ulonglong2*)(hrow + 4);  // b-pairs (4,5),(6,7)
            const float* wrow = wsc + kk * 64 + lnd;
            ulonglong2 wab = *(const ulonglong2*)(wrow);     // (w0,w0),(w1,w1)
            ulonglong2 wcd = *(const ulonglong2*)(wrow + 4); // (w2,w2),(w3,w3)
            ffma2(acc[0][0], hA.x, wab.x); ffma2(acc[1][0], hA.y, wab.x);
            ffma2(acc[2][0], hB.x, wab.x); ffma2(acc[3][0], hB.y, wab.x);
            ffma2(acc[0][1], hA.x, wab.y); ffma2(acc[1][1], hA.y, wab.y);
            ffma2(acc[2][1], hB.x, wab.y); ffma2(acc[3][1], hB.y, wab.y);
            ffma2(acc[0][2], hA.x, wcd.x); ffma2(acc[1][2], hA.y, wcd.x);
            ffma2(acc[2][2], hB.x, wcd.x); ffma2(acc[3][2], hB.y, wcd.x);
            ffma2(acc[0][3], hA.x, wcd.y); ffma2(acc[1][3], hA.y, wcd.y);
            ffma2(acc[2][3], hB.x, wcd.y); ffma2(acc[3][3], hB.y, wcd.y);
        }
        // no trailing sync: next iter stores into the other buffer
    }
}

// Unpack f32x2 accumulators into a [64][36] partial buffer (float4 rows).
__device__ __forceinline__ void store_part(float* __restrict__ dst,
                                           int b0, int ln0, ull (&acc)[4][4])
{
#pragma unroll
    for (int bp = 0; bp < 4; bp++) {
        float2 v0 = unpack2(acc[bp][0]);
        float2 v1 = unpack2(acc[bp][1]);
        float2 v2 = unpack2(acc[bp][2]);
        float2 v3 = unpack2(acc[bp][3]);
        float4 lo, hi;
        lo.x = v0.x; lo.y = v1.x; lo.z = v2.x; lo.w = v3.x;
        hi.x = v0.y; hi.y = v1.y; hi.z = v2.y; hi.w = v3.y;
        *(float4*)&dst[(b0 + 2 * bp) * 36 + ln0]     = lo;
        *(float4*)&dst[(b0 + 2 * bp + 1) * 36 + ln0] = hi;
    }
}

__global__ __launch_bounds__(NTH) void lstm_rec(
    const float* __restrict__ bi1, const float* __restrict__ bh1,
    float* __restrict__ out)
{
    extern __shared__ __align__(16) float smem[];
    float* const pool  = smem;                              // 32,768 (tiles/partials union)
    float* const gsm   = smem + POOL_FLOATS;                // 2,304
    float* const cs    = smem + POOL_FLOATS + 2304;         // 1,024
    float* const bsum1 = smem + POOL_FLOATS + 2304 + 1024;  // 32

    const int tid = threadIdx.x;
    const int jbase = blockIdx.x * 8;
    const int kgrp = tid >> 6;
    const int wtid = tid & 63;
    const int kbase = kgrp * 128;
    const int b0  = (wtid >> 3) * 8;
    const int ln0 = (wtid & 7) * 4;
    const int pb = tid >> 3, pj = tid & 7;    // pointwise item (b, jj)
    float* const tb = pool + TILE_OFF(kgrp);
    float* const pdst = (kgrp == 0) ? gsm : (pool + PART_OFF(kgrp));
    const size_t hoff = (size_t)kbase * Bz;
    const size_t woff = ((size_t)blockIdx.x * Hz + kbase) * 32;
    const float* const WT0 = g_WT[0] + woff;   // Wh0
    const float* const WT1 = g_WT[1] + woff;   // Wi1
    const float* const WT2 = g_WT[2] + woff;   // Wh1
    unsigned sense = g_sense;

    if (tid < 32) {
        int n = (tid >> 3) * Hz + jbase + (tid & 7);
        bsum1[tid] = bi1[n] + bh1[n];
    }
    cs[tid] = 0.f;
    cs[tid + 512] = 0.f;
    for (int idx = blockIdx.x * NTH + tid; idx < Bz * Hz; idx += NBLK * NTH) {
        g_h0T[0][idx] = 0.f;
        g_h1T[0][idx] = 0.f;
    }
    grid_bar(sense);

    for (int t = 0; t < Tz; t++) {
        const int rb = t & 1, wb = rb ^ 1;

        // prefetch this step's g_pre values (latency hidden behind L0 GEMM)
        float pre[4];
        {
            const float* p = &g_pre[((size_t)(t * Bz + pb)) * Gz + jbase + pj];
#pragma unroll
            for (int g = 0; g < 4; g++) pre[g] = p[g * Hz];
        }

        // ---------------- layer 0: gates = g_pre[t] + h0_prev @ Wh0^T ----------------
        ull acc[4][4];
#pragma unroll
        for (int bp = 0; bp < 4; bp++)
#pragma unroll
            for (int j = 0; j < 4; j++) acc[bp][j] = 0ull;
        gemm_ks(g_h0T[rb] + hoff, WT0, wtid, acc, tb);
        __syncthreads();                 // all tile reads done -> partials may overwrite
        store_part(pdst, b0, ln0, acc);
        __syncthreads();
        for (int i = tid; i < 2304; i += NTH) {   // reduce 8 partials into gsm
            float v = gsm[i];
#pragma unroll
            for (int g = 1; g < 8; g++) v += pool[PART_OFF(g) + i];
            gsm[i] = v;
        }
        __syncthreads();
        {
            const float* g = &gsm[pb * 36 + pj];
            float gi = g[0]  + pre[0];
            float gf = g[8]  + pre[1];
            float gg = g[16] + pre[2];
            float go = g[24] + pre[3];
            float c  = cs[tid];
            float cn = sigm(gf) * c + sigm(gi) * tanh_f(gg);
            float hn = sigm(go) * tanh_f(cn);
            cs[tid] = cn;
            g_h0T[wb][(jbase + pj) * Bz + pb] = hn;   // transposed write
            if (t == Tz - 1) {
                out[OUT_HOFF + pb * Hz + jbase + pj] = hn;
                out[OUT_COFF + pb * Hz + jbase + pj] = cn;
            }
        }
        grid_bar(sense);

        // ------- layer 1: gates = h0_cur @ Wi1^T + h1_prev @ Wh1^T + b1 -------
#pragma unroll
        for (int bp = 0; bp < 4; bp++)
#pragma unroll
            for (int j = 0; j < 4; j++) acc[bp][j] = 0ull;
        gemm_ks(g_h0T[wb] + hoff, WT1, wtid, acc, tb);  // current h0
        gemm_ks(g_h1T[rb] + hoff, WT2, wtid, acc, tb);  // previous h1
        __syncthreads();
        store_part(pdst, b0, ln0, acc);
        __syncthreads();
        for (int i = tid; i < 2304; i += NTH) {
            float v = gsm[i];
#pragma unroll
            for (int g = 1; g < 8; g++) v += pool[PART_OFF(g) + i];
            gsm[i] = v;
        }
        __syncthreads();
        {
            const float* g = &gsm[pb * 36 + pj];
            float gi = g[0]  + bsum1[pj];
            float gf = g[8]  + bsum1[8 + pj];
            float gg = g[16] + bsum1[16 + pj];
            float go = g[24] + bsum1[24 + pj];
            float c  = cs[512 + tid];
            float cn = sigm(gf) * c + sigm(gi) * tanh_f(gg);
            float hn = sigm(go) * tanh_f(cn);
            cs[512 + tid] = cn;
            g_h1T[wb][(jbase + pj) * Bz + pb] = hn;   // transposed write
            out[(size_t)(pb * Tz + t) * Hz + jbase + pj] = hn;   // top-layer output
            if (t == Tz - 1) {
                out[OUT_HOFF + Bz * Hz + pb * Hz + jbase + pj] = hn;
                out[OUT_COFF + Bz * Hz + pb * Hz + jbase + pj] = cn;
            }
        }
        grid_bar(sense);
    }
}

// ============================================================================
extern "C" void kernel_launch(void* const* d_in, const int* in_sizes, int n_in,
                              void* d_out, int out_size)
{
    const float* x   = (const float*)d_in[0];
    const float* Wi0 = (const float*)d_in[1];
    const float* Wh0 = (const float*)d_in[2];
    const float* bi0 = (const float*)d_in[3];
    const float* bh0 = (const float*)d_in[4];
    const float* Wi1 = (const float*)d_in[5];
    const float* Wh1 = (const float*)d_in[6];
    const float* bi1 = (const float*)d_in[7];
    const float* bh1 = (const float*)d_in[8];
    float* out = (float*)d_out;

    // raise dynamic SMEM cap (idempotent; not an allocation)
    static int smem_set = 0;
    if (!smem_set) {
        cudaFuncSetAttribute(lstm_rec, cudaFuncAttributeMaxDynamicSharedMemorySize,
                             SMEM_BYTES);
        smem_set = 1;
    }

    dim3 gwt(NBLK, Hz / 32, 3);             // weight transpose (stream-ordered)
    lstm_wt<<<gwt, 256>>>(Wh0, Wi1, Wh1);
    dim3 gpre(Gz / 128, (Bz * Tz) / 128);   // (32, 256)
    lstm_pre<<<gpre, 256>>>(x, Wi0, bi0, bh0);
    lstm_rec<<<NBLK, NTH, SMEM_BYTES>>>(bi1, bh1, out);
}

// round 14
// speedup vs baseline: 1.5926x; 1.5926x over previous
#include <cuda_runtime.h>

#define Bz 64
#define Tz 512
#define Fz 512
#define Hz 1024
#define Gz 4096   // 4*H
#define NBLK 128
#define NTH 512
#define OUT_HOFF (Bz*Tz*Hz)                 // 33,554,432
#define OUT_COFF (OUT_HOFF + 2*Bz*Hz)       // + 131,072

typedef unsigned long long ull;

// ---------------- static device scratch (no allocations allowed) ----------------
__device__ float g_pre[(size_t)Tz * Bz * Gz];       // [T][B][4H] input-GEMM + biases
__device__ float g_WT[3][(size_t)NBLK * Hz * 32];   // transposed weights: [jblk][k][32 ln]
__device__ float g_h0T[2][Hz * Bz];                 // layer0 h, TRANSPOSED [k][b]
__device__ float g_h1T[2][Hz * Bz];                 // layer1 h, TRANSPOSED [k][b]
__device__ unsigned g_count;
__device__ volatile unsigned g_sense;

// fast sigmoid / tanh: __expf (MUFU.EX2) + __fdividef (MUFU.RCP), ~1e-7 rel err.
__device__ __forceinline__ float sigm(float x) {
    return __fdividef(1.f, 1.f + __expf(-x));
}
__device__ __forceinline__ float tanh_f(float x) {
    float a = fabsf(x);
    float e = __expf(-2.f * a);
    float t = __fdividef(1.f - e, 1.f + e);
    return copysignf(t, x);
}

// ---- packed fp32x2 FMA (sm_10x FFMA2; only reachable via PTX) ----
__device__ __forceinline__ void ffma2(ull &d, ull a, ull b) {
    asm("fma.rn.f32x2 %0, %1, %2, %0;" : "+l"(d) : "l"(a), "l"(b));
}
__device__ __forceinline__ ull pack2(float x, float y) {
    ull r; asm("mov.b64 %0, {%1, %2};" : "=l"(r) : "f"(x), "f"(y)); return r;
}
__device__ __forceinline__ ull dup2(float x) { return pack2(x, x); }
__device__ __forceinline__ float2 unpack2(ull v) {
    float2 r; asm("mov.b64 {%0, %1}, %2;" : "=f"(r.x), "=f"(r.y) : "l"(v)); return r;
}

// Grid-wide barrier. Grid=128 blocks <= SM count => all co-resident, no deadlock.
__device__ __forceinline__ void grid_bar(unsigned &sense) {
    __syncthreads();
    if (threadIdx.x == 0) {
        unsigned s = sense + 1u;
        sense = s;
        __threadfence();
        unsigned arr = atomicAdd(&g_count, 1u);
        if (arr == gridDim.x - 1) {
            g_count = 0;
            __threadfence();
            g_sense = s;
        } else {
            while (g_sense != s) { }
            __threadfence();
        }
    }
    __syncthreads();
}

// ============================================================================
// Weight pre-transpose: g_WT[m][jblk][k][ln] = W[(ln>>3)*H + jblk*8 + (ln&7)][k]
// ============================================================================
__global__ __launch_bounds__(256) void lstm_wt(
    const float* __restrict__ W0, const float* __restrict__ W1,
    const float* __restrict__ W2)
{
    __shared__ float tile[32][33];
    const int jblk = blockIdx.x;
    const int k0   = blockIdx.y * 32;
    const int m    = blockIdx.z;
    const float* W = (m == 0) ? W0 : (m == 1) ? W1 : W2;
    float* dst = g_WT[m];
    const int lane = threadIdx.x & 31, grp = threadIdx.x >> 5;
#pragma unroll
    for (int i = 0; i < 4; i++) {
        int ln = grp + i * 8;
        int row = (ln >> 3) * Hz + jblk * 8 + (ln & 7);
        tile[ln][lane] = W[(size_t)row * Hz + k0 + lane];   // coalesced over k
    }
    __syncthreads();
#pragma unroll
    for (int i = 0; i < 4; i++) {
        int k = grp + i * 8;
        dst[((size_t)jblk * Hz + k0 + k) * 32 + lane] = tile[lane][k];  // coalesced over ln
    }
}

// ============================================================================
// Phase A: g_pre[t][b][n] = sum_k x[b][t][k] * Wi0[n][k] + bi0[n] + bh0[n]
// (unchanged — not the bottleneck)
// ============================================================================
__global__ __launch_bounds__(256) void lstm_pre(
    const float* __restrict__ x, const float* __restrict__ Wi0,
    const float* __restrict__ bi0, const float* __restrict__ bh0)
{
    __shared__ float As[16][132];
    __shared__ float Bs[16][132];

    const int tid = threadIdx.x;
    const int n0 = blockIdx.x * 128;
    const int m0 = blockIdx.y * 128;
    const int ty = tid >> 4, tx = tid & 15;

    const int r0 = tid >> 2,          kq0 = tid & 3;
    const int r1 = (tid + 256) >> 2,  kq1 = (tid + 256) & 3;
    const int gr0 = m0 + r0, gr1 = m0 + r1;
    const float* xa0 = &x[((size_t)((gr0 & 63) * Tz + (gr0 >> 6))) * Fz + kq0 * 4];
    const float* xa1 = &x[((size_t)((gr1 & 63) * Tz + (gr1 >> 6))) * Fz + kq1 * 4];
    const float* wb0 = &Wi0[((size_t)(n0 + r0)) * Fz + kq0 * 4];
    const float* wb1 = &Wi0[((size_t)(n0 + r1)) * Fz + kq1 * 4];

    ull acc2[4][8];
#pragma unroll
    for (int p = 0; p < 4; p++)
#pragma unroll
        for (int j = 0; j < 8; j++) acc2[p][j] = 0ull;

    float4 pa0 = *(const float4*)xa0;
    float4 pa1 = *(const float4*)xa1;
    float4 pb0 = *(const float4*)wb0;
    float4 pb1 = *(const float4*)wb1;

    for (int kc = 0; kc < Fz / 16; kc++) {
        __syncthreads();
        As[kq0 * 4 + 0][r0] = pa0.x; As[kq0 * 4 + 1][r0] = pa0.y;
        As[kq0 * 4 + 2][r0] = pa0.z; As[kq0 * 4 + 3][r0] = pa0.w;
        As[kq1 * 4 + 0][r1] = pa1.x; As[kq1 * 4 + 1][r1] = pa1.y;
        As[kq1 * 4 + 2][r1] = pa1.z; As[kq1 * 4 + 3][r1] = pa1.w;
        Bs[kq0 * 4 + 0][r0] = pb0.x; Bs[kq0 * 4 + 1][r0] = pb0.y;
        Bs[kq0 * 4 + 2][r0] = pb0.z; Bs[kq0 * 4 + 3][r0] = pb0.w;
        Bs[kq1 * 4 + 0][r1] = pb1.x; Bs[kq1 * 4 + 1][r1] = pb1.y;
        Bs[kq1 * 4 + 2][r1] = pb1.z; Bs[kq1 * 4 + 3][r1] = pb1.w;
        __syncthreads();
        if (kc < Fz / 16 - 1) {
            int off = (kc + 1) * 16;
            pa0 = *(const float4*)(xa0 + off);
            pa1 = *(const float4*)(xa1 + off);
            pb0 = *(const float4*)(wb0 + off);
            pb1 = *(const float4*)(wb1 + off);
        }
#pragma unroll
        for (int kk = 0; kk < 16; kk++) {
            ulonglong2 a01 = *(const ulonglong2*)&As[kk][ty * 8];
            ulonglong2 a23 = *(const ulonglong2*)&As[kk][ty * 8 + 4];
            float bb[8];
            *(float4*)&bb[0] = *(const float4*)&Bs[kk][tx * 8];
            *(float4*)&bb[4] = *(const float4*)&Bs[kk][tx * 8 + 4];
#pragma unroll
            for (int j = 0; j < 8; j++) {
                ull wd = dup2(bb[j]);
                ffma2(acc2[0][j], a01.x, wd);
                ffma2(acc2[1][j], a01.y, wd);
                ffma2(acc2[2][j], a23.x, wd);
                ffma2(acc2[3][j], a23.y, wd);
            }
        }
    }

    float accf[8][8];
#pragma unroll
    for (int p = 0; p < 4; p++)
#pragma unroll
        for (int j = 0; j < 8; j++) {
            float2 v = unpack2(acc2[p][j]);
            accf[2 * p][j] = v.x;
            accf[2 * p + 1][j] = v.y;
        }

    float bsv[8];
#pragma unroll
    for (int j = 0; j < 8; j++) {
        int n = n0 + tx * 8 + j;
        bsv[j] = bi0[n] + bh0[n];
    }
#pragma unroll
    for (int i = 0; i < 8; i++) {
        size_t off = (size_t)(m0 + ty * 8 + i) * Gz + n0 + tx * 8;
        float4 v0, v1;
        v0.x = accf[i][0] + bsv[0]; v0.y = accf[i][1] + bsv[1];
        v0.z = accf[i][2] + bsv[2]; v0.w = accf[i][3] + bsv[3];
        v1.x = accf[i][4] + bsv[4]; v1.y = accf[i][5] + bsv[5];
        v1.z = accf[i][6] + bsv[6]; v1.w = accf[i][7] + bsv[7];
        *(float4*)&g_pre[off]     = v0;
        *(float4*)&g_pre[off + 4] = v1;
    }
}

// ============================================================================
// Persistent recurrent kernel, 512 threads = 8 k-groups x 64 threads
// (R12 structure: single-buffered tiles, 2 syncs/kc, ws 32-float rows).
// NEW: h tile bank-swizzled — row stride 68 floats, columns >=32 shifted +4,
// so the 8 b-group LDS.128 reads per warp hit 8 DISTINCT bank quads (1 wf,
// was 2). Store side accepts 2-way (stores are 6x rarer than loads).
// ============================================================================
#define HROW 68
// tiles: hs[g] 16*68=1088 + ws[g] 512 => 1600/group, 12800 total
// partials (union): g>=1 at (g-1)*2304, 16128 total => pool = 16128
#define POOL_FLOATS 16128
#define HS_OFF(g)   ((g) * 1600)
#define WS_OFF(g)   ((g) * 1600 + 1088)
#define PART_OFF(g) (((g) - 1) * 2304)
#define SMEM_BYTES  ((POOL_FLOATS + 2304 + 1024 + 32) * 4)

__device__ __forceinline__ void gemm_ks(
    const float* __restrict__ hT,   // group's h slice: [(128k) x 64b] contiguous
    const float* __restrict__ WT,   // group's w slice: [(128k) x 32ln] contiguous
    int wtid, ull (&acc)[4][4],
    float* __restrict__ hs, float* __restrict__ ws)
{
    const int b0  = (wtid >> 3) * 8;
    const int bswz = b0 + ((b0 >= 32) ? 4 : 0);   // swizzled load column
    const int ln0 = (wtid & 7) * 4;
    const int h4  = wtid * 4;
    // swizzled store slot: flat f = wtid*4 -> row f/64, col f%64 (+4 if col>=32)
    const int sr = h4 >> 6;
    const int sc = h4 & 63;
    const int sdst = sr * HROW + sc + ((sc >= 32) ? 4 : 0);

    float4 ph0 = *(const float4*)(hT + h4);
    float4 ph1 = *(const float4*)(hT + 256 + h4);
    float4 ph2 = *(const float4*)(hT + 512 + h4);
    float4 ph3 = *(const float4*)(hT + 768 + h4);
    float4 pw0 = *(const float4*)(WT + h4);
    float4 pw1 = *(const float4*)(WT + 256 + h4);

    for (int kc = 0; kc < 8; kc++) {
        __syncthreads();        // previous tile fully consumed
        *(float4*)(hs + sdst)            = ph0;   // +256 floats = +4 rows
        *(float4*)(hs + 4 * HROW + sdst) = ph1;
        *(float4*)(hs + 8 * HROW + sdst) = ph2;
        *(float4*)(hs + 12 * HROW + sdst) = ph3;
        *(float4*)(ws + h4)       = pw0;
        *(float4*)(ws + 256 + h4) = pw1;
        __syncthreads();
        if (kc < 7) {           // prefetch next tile (latency overlaps compute)
            const float* hn = hT + (kc + 1) * 1024;
            const float* wn = WT + (kc + 1) * 512;
            ph0 = *(const float4*)(hn + h4);
            ph1 = *(const float4*)(hn + 256 + h4);
            ph2 = *(const float4*)(hn + 512 + h4);
            ph3 = *(const float4*)(hn + 768 + h4);
            pw0 = *(const float4*)(wn + h4);
            pw1 = *(const float4*)(wn + 256 + h4);
        }
#pragma unroll 4
        for (int kk = 0; kk < 16; kk++) {
            const float* hrow = hs + kk * HROW + bswz;
            ulonglong2 hA = *(const ulonglong2*)(hrow);      // b-pairs (0,1),(2,3)
            ulonglong2 hB = *(const ulonglong2*)(hrow + 4);  // b-pairs (4,5),(6,7)
            float4 wv = *(const float4*)(ws + kk * 32 + ln0);
            ull w0 = dup2(wv.x), w1 = dup2(wv.y), w2 = dup2(wv.z), w3 = dup2(wv.w);
            ffma2(acc[0][0], hA.x, w0); ffma2(acc[1][0], hA.y, w0);
            ffma2(acc[2][0], hB.x, w0); ffma2(acc[3][0], hB.y, w0);
            ffma2(acc[0][1], hA.x, w1); ffma2(acc[1][1], hA.y, w1);
            ffma2(acc[2][1], hB.x, w1); ffma2(acc[3][1], hB.y, w1);
            ffma2(acc[0][2], hA.x, w2); ffma2(acc[1][2], hA.y, w2);
            ffma2(acc[2][2], hB.x, w2); ffma2(acc[3][2], hB.y, w2);
            ffma2(acc[0][3], hA.x, w3); ffma2(acc[1][3], hA.y, w3);
            ffma2(acc[2][3], hB.x, w3); ffma2(acc[3][3], hB.y, w3);
        }
    }
}

// Unpack f32x2 accumulators into a [64][36] partial buffer (float4 rows).
__device__ __forceinline__ void store_part(float* __restrict__ dst,
                                           int b0, int ln0, ull (&acc)[4][4])
{
#pragma unroll
    for (int bp = 0; bp < 4; bp++) {
        float2 v0 = unpack2(acc[bp][0]);
        float2 v1 = unpack2(acc[bp][1]);
        float2 v2 = unpack2(acc[bp][2]);
        float2 v3 = unpack2(acc[bp][3]);
        float4 lo, hi;
        lo.x = v0.x; lo.y = v1.x; lo.z = v2.x; lo.w = v3.x;
        hi.x = v0.y; hi.y = v1.y; hi.z = v2.y; hi.w = v3.y;
        *(float4*)&dst[(b0 + 2 * bp) * 36 + ln0]     = lo;
        *(float4*)&dst[(b0 + 2 * bp + 1) * 36 + ln0] = hi;
    }
}

__global__ __launch_bounds__(NTH) void lstm_rec(
    const float* __restrict__ bi1, const float* __restrict__ bh1,
    float* __restrict__ out)
{
    extern __shared__ __align__(16) float smem[];
    float* const pool  = smem;                              // 16,128 (union)
    float* const gsm   = smem + POOL_FLOATS;                // 2,304
    float* const cs    = smem + POOL_FLOATS + 2304;         // 1,024
    float* const bsum1 = smem + POOL_FLOATS + 2304 + 1024;  // 32

    const int tid = threadIdx.x;
    const int jbase = blockIdx.x * 8;
    const int kgrp = tid >> 6;
    const int wtid = tid & 63;
    const int kbase = kgrp * 128;
    const int b0  = (wtid >> 3) * 8;
    const int ln0 = (wtid & 7) * 4;
    const int pb = tid >> 3, pj = tid & 7;    // pointwise item (b, jj)
    float* const hsp = pool + HS_OFF(kgrp);
    float* const wsp = pool + WS_OFF(kgrp);
    float* const pdst = (kgrp == 0) ? gsm : (pool + PART_OFF(kgrp));
    const size_t hoff = (size_t)kbase * Bz;
    const size_t woff = ((size_t)blockIdx.x * Hz + kbase) * 32;
    const float* const WT0 = g_WT[0] + woff;   // Wh0
    const float* const WT1 = g_WT[1] + woff;   // Wi1
    const float* const WT2 = g_WT[2] + woff;   // Wh1
    unsigned sense = g_sense;

    if (tid < 32) {
        int n = (tid >> 3) * Hz + jbase + (tid & 7);
        bsum1[tid] = bi1[n] + bh1[n];
    }
    cs[tid] = 0.f;
    cs[tid + 512] = 0.f;
    for (int idx = blockIdx.x * NTH + tid; idx < Bz * Hz; idx += NBLK * NTH) {
        g_h0T[0][idx] = 0.f;
        g_h1T[0][idx] = 0.f;
    }
    grid_bar(sense);

    for (int t = 0; t < Tz; t++) {
        const int rb = t & 1, wb = rb ^ 1;

        // prefetch this step's g_pre values (latency hidden behind L0 GEMM)
        float pre[4];
        {
            const float* p = &g_pre[((size_t)(t * Bz + pb)) * Gz + jbase + pj];
#pragma unroll
            for (int g = 0; g < 4; g++) pre[g] = p[g * Hz];
        }

        // ---------------- layer 0: gates = g_pre[t] + h0_prev @ Wh0^T ----------------
        ull acc[4][4];
#pragma unroll
        for (int bp = 0; bp < 4; bp++)
#pragma unroll
            for (int j = 0; j < 4; j++) acc[bp][j] = 0ull;
        gemm_ks(g_h0T[rb] + hoff, WT0, wtid, acc, hsp, wsp);
        __syncthreads();                 // tile reads done -> partials may overwrite
        store_part(pdst, b0, ln0, acc);
        __syncthreads();
        for (int i = tid; i < 2304; i += NTH) {   // reduce 8 partials into gsm
            float v = gsm[i];
#pragma unroll
            for (int g = 1; g < 8; g++) v += pool[PART_OFF(g) + i];
            gsm[i] = v;
        }
        __syncthreads();
        {
            const float* g = &gsm[pb * 36 + pj];
            float gi = g[0]  + pre[0];
            float gf = g[8]  + pre[1];
            float gg = g[16] + pre[2];
            float go = g[24] + pre[3];
            float c  = cs[tid];
            float cn = sigm(gf) * c + sigm(gi) * tanh_f(gg);
            float hn = sigm(go) * tanh_f(cn);
            cs[tid] = cn;
            g_h0T[wb][(jbase + pj) * Bz + pb] = hn;   // transposed write
            if (t == Tz - 1) {
                out[OUT_HOFF + pb * Hz + jbase + pj] = hn;
                out[OUT_COFF + pb * Hz + jbase + pj] = cn;
            }
        }
        grid_bar(sense);

        // ------- layer 1: gates = h0_cur @ Wi1^T + h1_prev @ Wh1^T + b1 -------
#pragma unroll
        for (int bp = 0; bp < 4; bp++)
#pragma unroll
            for (int j = 0; j < 4; j++) acc[bp][j] = 0ull;
        gemm_ks(g_h0T[wb] + hoff, WT1, wtid, acc, hsp, wsp);  // current h0
        gemm_ks(g_h1T[rb] + hoff, WT2, wtid, acc, hsp, wsp);  // previous h1
        __syncthreads();
        store_part(pdst, b0, ln0, acc);
        __syncthreads();
        for (int i = tid; i < 2304; i += NTH) {
            float v = gsm[i];
#pragma unroll
            for (int g = 1; g < 8; g++) v += pool[PART_OFF(g) + i];
            gsm[i] = v;
        }
        __syncthreads();
        {
            const float* g = &gsm[pb * 36 + pj];
            float gi = g[0]  + bsum1[pj];
            float gf = g[8]  + bsum1[8 + pj];
            float gg = g[16] + bsum1[16 + pj];
            float go = g[24] + bsum1[24 + pj];
            float c  = cs[512 + tid];
            float cn = sigm(gf) * c + sigm(gi) * tanh_f(gg);
            float hn = sigm(go) * tanh_f(cn);
            cs[512 + tid] = cn;
            g_h1T[wb][(jbase + pj) * Bz + pb] = hn;   // transposed write
            out[(size_t)(pb * Tz + t) * Hz + jbase + pj] = hn;   // top-layer output
            if (t == Tz - 1) {
                out[OUT_HOFF + Bz * Hz + pb * Hz + jbase + pj] = hn;
                out[OUT_COFF + Bz * Hz + pb * Hz + jbase + pj] = cn;
            }
        }
        grid_bar(sense);
    }
}

// ============================================================================
extern "C" void kernel_launch(void* const* d_in, const int* in_sizes, int n_in,
                              void* d_out, int out_size)
{
    const float* x   = (const float*)d_in[0];
    const float* Wi0 = (const float*)d_in[1];
    const float* Wh0 = (const float*)d_in[2];
    const float* bi0 = (const float*)d_in[3];
    const float* bh0 = (const float*)d_in[4];
    const float* Wi1 = (const float*)d_in[5];
    const float* Wh1 = (const float*)d_in[6];
    const float* bi1 = (const float*)d_in[7];
    const float* bh1 = (const float*)d_in[8];
    float* out = (float*)d_out;

    // raise dynamic SMEM cap (idempotent; not an allocation)
    static int smem_set = 0;
    if (!smem_set) {
        cudaFuncSetAttribute(lstm_rec, cudaFuncAttributeMaxDynamicSharedMemorySize,
                             SMEM_BYTES);
        smem_set = 1;
    }

    dim3 gwt(NBLK, Hz / 32, 3);             // weight transpose (stream-ordered)
    lstm_wt<<<gwt, 256>>>(Wh0, Wi1, Wh1);
    dim3 gpre(Gz / 128, (Bz * Tz) / 128);   // (32, 256)
    lstm_pre<<<gpre, 256>>>(x, Wi0, bi0, bh0);
    lstm_rec<<<NBLK, NTH, SMEM_BYTES>>>(bi1, bh1, out);
}

// round 15
// speedup vs baseline: 1.6004x; 1.0049x over previous
#include <cuda_runtime.h>

#define Bz 64
#define Tz 512
#define Fz 512
#define Hz 1024
#define Gz 4096   // 4*H
#define NBLK 128
#define NTH 512
#define OUT_HOFF (Bz*Tz*Hz)                 // 33,554,432
#define OUT_COFF (OUT_HOFF + 2*Bz*Hz)       // + 131,072

typedef unsigned long long ull;

// ---------------- static device scratch (no allocations allowed) ----------------
__device__ float g_pre[(size_t)Tz * Bz * Gz];       // [T][B][4H] input-GEMM + biases
__device__ float g_WT[3][(size_t)NBLK * Hz * 32];   // transposed weights: [jblk][k][32 ln]
__device__ float g_h0T[2][Hz * Bz];                 // layer0 h, TRANSPOSED [k][b]
__device__ float g_h1T[2][Hz * Bz];                 // layer1 h, TRANSPOSED [k][b]
__device__ unsigned g_count;
__device__ volatile unsigned g_sense;

// fast sigmoid / tanh: __expf (MUFU.EX2) + __fdividef (MUFU.RCP), ~1e-7 rel err.
__device__ __forceinline__ float sigm(float x) {
    return __fdividef(1.f, 1.f + __expf(-x));
}
__device__ __forceinline__ float tanh_f(float x) {
    float a = fabsf(x);
    float e = __expf(-2.f * a);
    float t = __fdividef(1.f - e, 1.f + e);
    return copysignf(t, x);
}

// ---- packed fp32x2 FMA (sm_10x FFMA2; only reachable via PTX) ----
__device__ __forceinline__ void ffma2(ull &d, ull a, ull b) {
    asm("fma.rn.f32x2 %0, %1, %2, %0;" : "+l"(d) : "l"(a), "l"(b));
}
__device__ __forceinline__ ull pack2(float x, float y) {
    ull r; asm("mov.b64 %0, {%1, %2};" : "=l"(r) : "f"(x), "f"(y)); return r;
}
__device__ __forceinline__ ull dup2(float x) { return pack2(x, x); }
__device__ __forceinline__ float2 unpack2(ull v) {
    float2 r; asm("mov.b64 {%0, %1}, %2;" : "=f"(r.x), "=f"(r.y) : "l"(v)); return r;
}

// Grid-wide barrier. Grid=128 blocks <= SM count => all co-resident, no deadlock.
__device__ __forceinline__ void grid_bar(unsigned &sense) {
    __syncthreads();
    if (threadIdx.x == 0) {
        unsigned s = sense + 1u;
        sense = s;
        __threadfence();
        unsigned arr = atomicAdd(&g_count, 1u);
        if (arr == gridDim.x - 1) {
            g_count = 0;
            __threadfence();
            g_sense = s;
        } else {
            while (g_sense != s) { }
            __threadfence();
        }
    }
    __syncthreads();
}

// ============================================================================
// Weight pre-transpose: g_WT[m][jblk][k][ln] = W[(ln>>3)*H + jblk*8 + (ln&7)][k]
// ============================================================================
__global__ __launch_bounds__(256) void lstm_wt(
    const float* __restrict__ W0, const float* __restrict__ W1,
    const float* __restrict__ W2)
{
    __shared__ float tile[32][33];
    const int jblk = blockIdx.x;
    const int k0   = blockIdx.y * 32;
    const int m    = blockIdx.z;
    const float* W = (m == 0) ? W0 : (m == 1) ? W1 : W2;
    float* dst = g_WT[m];
    const int lane = threadIdx.x & 31, grp = threadIdx.x >> 5;
#pragma unroll
    for (int i = 0; i < 4; i++) {
        int ln = grp + i * 8;
        int row = (ln >> 3) * Hz + jblk * 8 + (ln & 7);
        tile[ln][lane] = W[(size_t)row * Hz + k0 + lane];   // coalesced over k
    }
    __syncthreads();
#pragma unroll
    for (int i = 0; i < 4; i++) {
        int k = grp + i * 8;
        dst[((size_t)jblk * Hz + k0 + k) * 32 + lane] = tile[lane][k];  // coalesced over ln
    }
}

// ============================================================================
// Phase A: g_pre[t][b][n] = sum_k x[b][t][k] * Wi0[n][k] + bi0[n] + bh0[n]
// (unchanged — not the bottleneck)
// ============================================================================
__global__ __launch_bounds__(256) void lstm_pre(
    const float* __restrict__ x, const float* __restrict__ Wi0,
    const float* __restrict__ bi0, const float* __restrict__ bh0)
{
    __shared__ float As[16][132];
    __shared__ float Bs[16][132];

    const int tid = threadIdx.x;
    const int n0 = blockIdx.x * 128;
    const int m0 = blockIdx.y * 128;
    const int ty = tid >> 4, tx = tid & 15;

    const int r0 = tid >> 2,          kq0 = tid & 3;
    const int r1 = (tid + 256) >> 2,  kq1 = (tid + 256) & 3;
    const int gr0 = m0 + r0, gr1 = m0 + r1;
    const float* xa0 = &x[((size_t)((gr0 & 63) * Tz + (gr0 >> 6))) * Fz + kq0 * 4];
    const float* xa1 = &x[((size_t)((gr1 & 63) * Tz + (gr1 >> 6))) * Fz + kq1 * 4];
    const float* wb0 = &Wi0[((size_t)(n0 + r0)) * Fz + kq0 * 4];
    const float* wb1 = &Wi0[((size_t)(n0 + r1)) * Fz + kq1 * 4];

    ull acc2[4][8];
#pragma unroll
    for (int p = 0; p < 4; p++)
#pragma unroll
        for (int j = 0; j < 8; j++) acc2[p][j] = 0ull;

    float4 pa0 = *(const float4*)xa0;
    float4 pa1 = *(const float4*)xa1;
    float4 pb0 = *(const float4*)wb0;
    float4 pb1 = *(const float4*)wb1;

    for (int kc = 0; kc < Fz / 16; kc++) {
        __syncthreads();
        As[kq0 * 4 + 0][r0] = pa0.x; As[kq0 * 4 + 1][r0] = pa0.y;
        As[kq0 * 4 + 2][r0] = pa0.z; As[kq0 * 4 + 3][r0] = pa0.w;
        As[kq1 * 4 + 0][r1] = pa1.x; As[kq1 * 4 + 1][r1] = pa1.y;
        As[kq1 * 4 + 2][r1] = pa1.z; As[kq1 * 4 + 3][r1] = pa1.w;
        Bs[kq0 * 4 + 0][r0] = pb0.x; Bs[kq0 * 4 + 1][r0] = pb0.y;
        Bs[kq0 * 4 + 2][r0] = pb0.z; Bs[kq0 * 4 + 3][r0] = pb0.w;
        Bs[kq1 * 4 + 0][r1] = pb1.x; Bs[kq1 * 4 + 1][r1] = pb1.y;
        Bs[kq1 * 4 + 2][r1] = pb1.z; Bs[kq1 * 4 + 3][r1] = pb1.w;
        __syncthreads();
        if (kc < Fz / 16 - 1) {
            int off = (kc + 1) * 16;
            pa0 = *(const float4*)(xa0 + off);
            pa1 = *(const float4*)(xa1 + off);
            pb0 = *(const float4*)(wb0 + off);
            pb1 = *(const float4*)(wb1 + off);
        }
#pragma unroll
        for (int kk = 0; kk < 16; kk++) {
            ulonglong2 a01 = *(const ulonglong2*)&As[kk][ty * 8];
            ulonglong2 a23 = *(const ulonglong2*)&As[kk][ty * 8 + 4];
            float bb[8];
            *(float4*)&bb[0] = *(const float4*)&Bs[kk][tx * 8];
            *(float4*)&bb[4] = *(const float4*)&Bs[kk][tx * 8 + 4];
#pragma unroll
            for (int j = 0; j < 8; j++) {
                ull wd = dup2(bb[j]);
                ffma2(acc2[0][j], a01.x, wd);
                ffma2(acc2[1][j], a01.y, wd);
                ffma2(acc2[2][j], a23.x, wd);
                ffma2(acc2[3][j], a23.y, wd);
            }
        }
    }

    float accf[8][8];
#pragma unroll
    for (int p = 0; p < 4; p++)
#pragma unroll
        for (int j = 0; j < 8; j++) {
            float2 v = unpack2(acc2[p][j]);
            accf[2 * p][j] = v.x;
            accf[2 * p + 1][j] = v.y;
        }

    float bsv[8];
#pragma unroll
    for (int j = 0; j < 8; j++) {
        int n = n0 + tx * 8 + j;
        bsv[j] = bi0[n] + bh0[n];
    }
#pragma unroll
    for (int i = 0; i < 8; i++) {
        size_t off = (size_t)(m0 + ty * 8 + i) * Gz + n0 + tx * 8;
        float4 v0, v1;
        v0.x = accf[i][0] + bsv[0]; v0.y = accf[i][1] + bsv[1];
        v0.z = accf[i][2] + bsv[2]; v0.w = accf[i][3] + bsv[3];
        v1.x = accf[i][4] + bsv[4]; v1.y = accf[i][5] + bsv[5];
        v1.z = accf[i][6] + bsv[6]; v1.w = accf[i][7] + bsv[7];
        *(float4*)&g_pre[off]     = v0;
        *(float4*)&g_pre[off + 4] = v1;
    }
}

// ============================================================================
// Persistent recurrent kernel, 512 threads = 8 k-groups x 64 threads.
// R14 tile layout (h swizzled HROW=68, w rows 32 floats) + DOUBLE-BUFFERED
// tiles: ONE sync per kc (was 2), register prefetch gets a full-kc distance
// to cover L2 weight latency. Hazard-safe: at iter i+1 a fast warp stores
// buf(i+1)&1 while laggards compute buf i&1 — always different buffers.
// ============================================================================
#define HROW 68
// per-group tile region: hs0(1088) hs1(1088) ws0(512) ws1(512) = 3200 floats
// pool = max(8*3200, partial 16128) = 25600 floats (partials union tiles)
#define POOL_FLOATS 25600
#define TILE_OFF(g) ((g) * 3200)
#define PART_OFF(g) (((g) - 1) * 2304)
#define SMEM_BYTES  ((POOL_FLOATS + 2304 + 1024 + 32) * 4)

__device__ __forceinline__ void gemm_ks(
    const float* __restrict__ hT,   // group's h slice: [(128k) x 64b] contiguous
    const float* __restrict__ WT,   // group's w slice: [(128k) x 32ln] contiguous
    int wtid, ull (&acc)[4][4], float* __restrict__ tb)
{
    const int b0  = (wtid >> 3) * 8;
    const int bswz = b0 + ((b0 >= 32) ? 4 : 0);   // swizzled load column
    const int ln0 = (wtid & 7) * 4;
    const int h4  = wtid * 4;
    // swizzled store slot: flat f = wtid*4 -> row f/64, col f%64 (+4 if col>=32)
    const int sr = h4 >> 6;
    const int sc = h4 & 63;
    const int sdst = sr * HROW + sc + ((sc >= 32) ? 4 : 0);

    float4 ph0 = *(const float4*)(hT + h4);
    float4 ph1 = *(const float4*)(hT + 256 + h4);
    float4 ph2 = *(const float4*)(hT + 512 + h4);
    float4 ph3 = *(const float4*)(hT + 768 + h4);
    float4 pw0 = *(const float4*)(WT + h4);
    float4 pw1 = *(const float4*)(WT + 256 + h4);

    for (int kc = 0; kc < 8; kc++) {
        float* const hs = tb + ((kc & 1) ? 1088 : 0);
        float* const ws = tb + 2176 + ((kc & 1) ? 512 : 0);
        *(float4*)(hs + sdst)             = ph0;
        *(float4*)(hs + 4 * HROW + sdst)  = ph1;
        *(float4*)(hs + 8 * HROW + sdst)  = ph2;
        *(float4*)(hs + 12 * HROW + sdst) = ph3;
        *(float4*)(ws + h4)       = pw0;
        *(float4*)(ws + 256 + h4) = pw1;
        __syncthreads();    // single sync: this buffer ready, other buffer free
        if (kc < 7) {       // prefetch next tile; consumed AFTER this kc's compute
            const float* hn = hT + (kc + 1) * 1024;
            const float* wn = WT + (kc + 1) * 512;
            ph0 = *(const float4*)(hn + h4);
            ph1 = *(const float4*)(hn + 256 + h4);
            ph2 = *(const float4*)(hn + 512 + h4);
            ph3 = *(const float4*)(hn + 768 + h4);
            pw0 = *(const float4*)(wn + h4);
            pw1 = *(const float4*)(wn + 256 + h4);
        }
#pragma unroll 4
        for (int kk = 0; kk < 16; kk++) {
            const float* hrow = hs + kk * HROW + bswz;
            ulonglong2 hA = *(const ulonglong2*)(hrow);      // b-pairs (0,1),(2,3)
            ulonglong2 hB = *(const ulonglong2*)(hrow + 4);  // b-pairs (4,5),(6,7)
            float4 wv = *(const float4*)(ws + kk * 32 + ln0);
            ull w0 = dup2(wv.x), w1 = dup2(wv.y), w2 = dup2(wv.z), w3 = dup2(wv.w);
            ffma2(acc[0][0], hA.x, w0); ffma2(acc[1][0], hA.y, w0);
            ffma2(acc[2][0], hB.x, w0); ffma2(acc[3][0], hB.y, w0);
            ffma2(acc[0][1], hA.x, w1); ffma2(acc[1][1], hA.y, w1);
            ffma2(acc[2][1], hB.x, w1); ffma2(acc[3][1], hB.y, w1);
            ffma2(acc[0][2], hA.x, w2); ffma2(acc[1][2], hA.y, w2);
            ffma2(acc[2][2], hB.x, w2); ffma2(acc[3][2], hB.y, w2);
            ffma2(acc[0][3], hA.x, w3); ffma2(acc[1][3], hA.y, w3);
            ffma2(acc[2][3], hB.x, w3); ffma2(acc[3][3], hB.y, w3);
        }
        // no trailing sync: next iter writes the OTHER buffer
    }
}

// Unpack f32x2 accumulators into a [64][36] partial buffer (float4 rows).
__device__ __forceinline__ void store_part(float* __restrict__ dst,
                                           int b0, int ln0, ull (&acc)[4][4])
{
#pragma unroll
    for (int bp = 0; bp < 4; bp++) {
        float2 v0 = unpack2(acc[bp][0]);
        float2 v1 = unpack2(acc[bp][1]);
        float2 v2 = unpack2(acc[bp][2]);
        float2 v3 = unpack2(acc[bp][3]);
        float4 lo, hi;
        lo.x = v0.x; lo.y = v1.x; lo.z = v2.x; lo.w = v3.x;
        hi.x = v0.y; hi.y = v1.y; hi.z = v2.y; hi.w = v3.y;
        *(float4*)&dst[(b0 + 2 * bp) * 36 + ln0]     = lo;
        *(float4*)&dst[(b0 + 2 * bp + 1) * 36 + ln0] = hi;
    }
}

__global__ __launch_bounds__(NTH) void lstm_rec(
    const float* __restrict__ bi1, const float* __restrict__ bh1,
    float* __restrict__ out)
{
    extern __shared__ __align__(16) float smem[];
    float* const pool  = smem;                              // 25,600 (tiles/partials union)
    float* const gsm   = smem + POOL_FLOATS;                // 2,304
    float* const cs    = smem + POOL_FLOATS + 2304;         // 1,024
    float* const bsum1 = smem + POOL_FLOATS + 2304 + 1024;  // 32

    const int tid = threadIdx.x;
    const int jbase = blockIdx.x * 8;
    const int kgrp = tid >> 6;
    const int wtid = tid & 63;
    const int kbase = kgrp * 128;
    const int b0  = (wtid >> 3) * 8;
    const int ln0 = (wtid & 7) * 4;
    const int pb = tid >> 3, pj = tid & 7;    // pointwise item (b, jj)
    float* const tb = pool + TILE_OFF(kgrp);
    float* const pdst = (kgrp == 0) ? gsm : (pool + PART_OFF(kgrp));
    const size_t hoff = (size_t)kbase * Bz;
    const size_t woff = ((size_t)blockIdx.x * Hz + kbase) * 32;
    const float* const WT0 = g_WT[0] + woff;   // Wh0
    const float* const WT1 = g_WT[1] + woff;   // Wi1
    const float* const WT2 = g_WT[2] + woff;   // Wh1
    unsigned sense = g_sense;

    if (tid < 32) {
        int n = (tid >> 3) * Hz + jbase + (tid & 7);
        bsum1[tid] = bi1[n] + bh1[n];
    }
    cs[tid] = 0.f;
    cs[tid + 512] = 0.f;
    for (int idx = blockIdx.x * NTH + tid; idx < Bz * Hz; idx += NBLK * NTH) {
        g_h0T[0][idx] = 0.f;
        g_h1T[0][idx] = 0.f;
    }
    grid_bar(sense);

    for (int t = 0; t < Tz; t++) {
        const int rb = t & 1, wb = rb ^ 1;

        // prefetch this step's g_pre values (latency hidden behind L0 GEMM)
        float pre[4];
        {
            const float* p = &g_pre[((size_t)(t * Bz + pb)) * Gz + jbase + pj];
#pragma unroll
            for (int g = 0; g < 4; g++) pre[g] = p[g * Hz];
        }

        // ---------------- layer 0: gates = g_pre[t] + h0_prev @ Wh0^T ----------------
        ull acc[4][4];
#pragma unroll
        for (int bp = 0; bp < 4; bp++)
#pragma unroll
            for (int j = 0; j < 4; j++) acc[bp][j] = 0ull;
        gemm_ks(g_h0T[rb] + hoff, WT0, wtid, acc, tb);
        __syncthreads();                 // all tile reads done -> partials may overwrite
        store_part(pdst, b0, ln0, acc);
        __syncthreads();
        for (int i = tid; i < 2304; i += NTH) {   // reduce 8 partials into gsm
            float v = gsm[i];
#pragma unroll
            for (int g = 1; g < 8; g++) v += pool[PART_OFF(g) + i];
            gsm[i] = v;
        }
        __syncthreads();
        {
            const float* g = &gsm[pb * 36 + pj];
            float gi = g[0]  + pre[0];
            float gf = g[8]  + pre[1];
            float gg = g[16] + pre[2];
            float go = g[24] + pre[3];
            float c  = cs[tid];
            float cn = sigm(gf) * c + sigm(gi) * tanh_f(gg);
            float hn = sigm(go) * tanh_f(cn);
            cs[tid] = cn;
            g_h0T[wb][(jbase + pj) * Bz + pb] = hn;   // transposed write
            if (t == Tz - 1) {
                out[OUT_HOFF + pb * Hz + jbase + pj] = hn;
                out[OUT_COFF + pb * Hz + jbase + pj] = cn;
            }
        }
        grid_bar(sense);

        // ------- layer 1: gates = h0_cur @ Wi1^T + h1_prev @ Wh1^T + b1 -------
#pragma unroll
        for (int bp = 0; bp < 4; bp++)
#pragma unroll
            for (int j = 0; j < 4; j++) acc[bp][j] = 0ull;
        gemm_ks(g_h0T[wb] + hoff, WT1, wtid, acc, tb);  // current h0
        gemm_ks(g_h1T[rb] + hoff, WT2, wtid, acc, tb);  // previous h1
        __syncthreads();
        store_part(pdst, b0, ln0, acc);
        __syncthreads();
        for (int i = tid; i < 2304; i += NTH) {
            float v = gsm[i];
#pragma unroll
            for (int g = 1; g < 8; g++) v += pool[PART_OFF(g) + i];
            gsm[i] = v;
        }
        __syncthreads();
        {
            const float* g = &gsm[pb * 36 + pj];
            float gi = g[0]  + bsum1[pj];
            float gf = g[8]  + bsum1[8 + pj];
            float gg = g[16] + bsum1[16 + pj];
            float go = g[24] + bsum1[24 + pj];
            float c  = cs[512 + tid];
            float cn = sigm(gf) * c + sigm(gi) * tanh_f(gg);
            float hn = sigm(go) * tanh_f(cn);
            cs[512 + tid] = cn;
            g_h1T[wb][(jbase + pj) * Bz + pb] = hn;   // transposed write
            out[(size_t)(pb * Tz + t) * Hz + jbase + pj] = hn;   // top-layer output
            if (t == Tz - 1) {
                out[OUT_HOFF + Bz * Hz + pb * Hz + jbase + pj] = hn;
                out[OUT_COFF + Bz * Hz + pb * Hz + jbase + pj] = cn;
            }
        }
        grid_bar(sense);
    }
}

// ============================================================================
extern "C" void kernel_launch(void* const* d_in, const int* in_sizes, int n_in,
                              void* d_out, int out_size)
{
    const float* x   = (const float*)d_in[0];
    const float* Wi0 = (const float*)d_in[1];
    const float* Wh0 = (const float*)d_in[2];
    const float* bi0 = (const float*)d_in[3];
    const float* bh0 = (const float*)d_in[4];
    const float* Wi1 = (const float*)d_in[5];
    const float* Wh1 = (const float*)d_in[6];
    const float* bi1 = (const float*)d_in[7];
    const float* bh1 = (const float*)d_in[8];
    float* out = (float*)d_out;

    // raise dynamic SMEM cap (idempotent; not an allocation)
    static int smem_set = 0;
    if (!smem_set) {
        cudaFuncSetAttribute(lstm_rec, cudaFuncAttributeMaxDynamicSharedMemorySize,
                             SMEM_BYTES);
        smem_set = 1;
    }

    dim3 gwt(NBLK, Hz / 32, 3);             // weight transpose (stream-ordered)
    lstm_wt<<<gwt, 256>>>(Wh0, Wi1, Wh1);
    dim3 gpre(Gz / 128, (Bz * Tz) / 128);   // (32, 256)
    lstm_pre<<<gpre, 256>>>(x, Wi0, bi0, bh0);
    lstm_rec<<<NBLK, NTH, SMEM_BYTES>>>(bi1, bh1, out);
}